// round 3
// baseline (speedup 1.0000x reference)
#include <cuda_runtime.h>
#include <cuda_fp16.h>
#include <cstdint>

#define NPTS 4096
#define NP1  4097
#define PAD  4104           // row stride (elements), 8-elem aligned -> 16B aligned rows for half
#define MU_SMALL (1.0f/8192.0f)
#define SCALE_OUT 8192.0f   // exp(-norm) = m+n
#define INV_SQRT_D 0.08838834764831845f  // 1/sqrt(128)

// ---------------- device scratch (no cudaMalloc allowed) ----------------
__device__ float              g_Ef [(size_t)NP1 * PAD];   // fp32 exp(couplings), padded
__device__ __half             g_Eh [(size_t)NP1 * PAD];   // fp16 copy (row-major)
__device__ __half             g_EhT[(size_t)NP1 * PAD];   // fp16 transpose
__device__ float              g_U[PAD];
__device__ float              g_V[PAD];
__device__ unsigned long long g_rowbest[NPTS];
__device__ unsigned long long g_colbest[NPTS];

// ---------------- init: bins, pads, V=1, colbest=0 ----------------
__global__ void init_k(const float* __restrict__ bin) {
    int idx = blockIdx.x * blockDim.x + threadIdx.x;
    float ea = __expf(bin[0]);
    __half eah = __float2half_rn(ea);
    __half zh  = __float2half_rn(0.0f);
    if (idx < PAD) {
        g_V[idx] = (idx < NP1) ? 1.0f : 0.0f;
        g_U[idx] = 0.0f;
    }
    if (idx < NPTS) g_colbest[idx] = 0ull;
    if (idx < NP1) {
        // bin column and bin row (corner covered by both, same value)
        g_Ef[(size_t)idx * PAD + NPTS] = ea;
        g_Eh[(size_t)idx * PAD + NPTS] = eah;
        g_Ef[(size_t)NPTS * PAD + idx] = ea;
        g_Eh[(size_t)NPTS * PAD + idx] = eah;
        // zero the padding columns so they never contribute to sums
        #pragma unroll
        for (int p = NP1; p < PAD; p++) {
            g_Ef[(size_t)idx * PAD + p] = 0.0f;
            g_Eh[(size_t)idx * PAD + p] = zh;
        }
    }
}

// ---------------- GEMM: C = (A^T B)/sqrt(128); E = exp(C) ----------------
// A = mdesc0 (128 x 4096) row-major, B = mdesc1 (128 x 4096) row-major.
// C[n][m] = sum_d A[d][n] * B[d][m].  Block tile 128x128, thread tile 8x8.
__global__ __launch_bounds__(256) void gemm_exp_k(const float* __restrict__ A,
                                                  const float* __restrict__ B) {
    __shared__ float As[16][128];
    __shared__ float Bs[16][128];
    int tid = threadIdx.x;
    int tx = tid & 15;
    int ty = tid >> 4;
    int n0 = blockIdx.y * 128;
    int m0 = blockIdx.x * 128;

    float acc[8][8];
    #pragma unroll
    for (int i = 0; i < 8; i++)
        #pragma unroll
        for (int j = 0; j < 8; j++) acc[i][j] = 0.0f;

    for (int kk = 0; kk < 128; kk += 16) {
        #pragma unroll
        for (int p = 0; p < 2; p++) {
            int v = tid + p * 256;        // 0..511  (512 float4 per tile)
            int r = v >> 5;               // 0..15
            int c4 = (v & 31) << 2;       // 0..124
            *(float4*)&As[r][c4] = *(const float4*)&A[(size_t)(kk + r) * 4096 + n0 + c4];
            *(float4*)&Bs[r][c4] = *(const float4*)&B[(size_t)(kk + r) * 4096 + m0 + c4];
        }
        __syncthreads();
        #pragma unroll
        for (int k = 0; k < 16; k++) {
            float a[8], b[8];
            *(float4*)&a[0] = *(float4*)&As[k][ty * 8];
            *(float4*)&a[4] = *(float4*)&As[k][ty * 8 + 4];
            *(float4*)&b[0] = *(float4*)&Bs[k][tx * 8];
            *(float4*)&b[4] = *(float4*)&Bs[k][tx * 8 + 4];
            #pragma unroll
            for (int i = 0; i < 8; i++)
                #pragma unroll
                for (int j = 0; j < 8; j++)
                    acc[i][j] = fmaf(a[i], b[j], acc[i][j]);
        }
        __syncthreads();
    }

    #pragma unroll
    for (int i = 0; i < 8; i++) {
        int n = n0 + ty * 8 + i;
        #pragma unroll
        for (int j = 0; j < 8; j++) {
            int m = m0 + tx * 8 + j;
            float e = __expf(acc[i][j] * INV_SQRT_D);
            g_Ef[(size_t)n * PAD + m] = e;
            g_Eh[(size_t)n * PAD + m] = __float2half_rn(e);
        }
    }
}

// ---------------- transpose Eh -> EhT (32x32 tiles) ----------------
__global__ void transpose_k() {
    __shared__ __half tile[32][33];
    int tx = threadIdx.x;        // 0..31
    int ty = threadIdx.y;        // 0..7
    int nBase = blockIdx.y * 32; // Eh row index base
    int mBase = blockIdx.x * 32; // Eh col index base
    #pragma unroll
    for (int jj = 0; jj < 32; jj += 8) {
        int n = nBase + ty + jj;
        int m = mBase + tx;
        __half v = __float2half_rn(0.0f);
        if (n < NP1 && m < PAD) v = g_Eh[(size_t)n * PAD + m];
        tile[ty + jj][tx] = v;
    }
    __syncthreads();
    #pragma unroll
    for (int jj = 0; jj < 32; jj += 8) {
        int m = mBase + ty + jj;   // EhT row
        int n = nBase + tx;        // EhT col
        if (m < NP1 && n < PAD) g_EhT[(size_t)m * PAD + n] = tile[tx][ty + jj];
    }
}

// ---------------- one Sinkhorn half-iteration (matvec + divide) ----------------
// dir==0: U = mu / (Eh  . V)      dir==1: V = nu / (EhT . U)
__global__ __launch_bounds__(512) void sink_pass_k(int dir) {
    __shared__ float sx[PAD];
    const __half* M  = dir ? g_EhT : g_Eh;
    const float*  xin  = dir ? g_U : g_V;
    float*        xout = dir ? g_V : g_U;

    int tid = threadIdx.x;
    for (int idx = tid; idx < PAD; idx += 512) sx[idx] = xin[idx];
    __syncthreads();

    int w = tid >> 5, lane = tid & 31;
    int row = blockIdx.x * 16 + w;
    if (row >= NP1) return;

    const __half* rp = M + (size_t)row * PAD;
    float acc = 0.0f;
    #pragma unroll 4
    for (int it = 0; it < 17; it++) {
        int base = (it * 32 + lane) * 8;
        if (base < PAD) {
            uint4 hv = *(const uint4*)(rp + base);   // 8 halves
            float4 v0 = *(float4*)&sx[base];
            float4 v1 = *(float4*)&sx[base + 4];
            float2 f0 = __half22float2(*(__half2*)&hv.x);
            float2 f1 = __half22float2(*(__half2*)&hv.y);
            float2 f2 = __half22float2(*(__half2*)&hv.z);
            float2 f3 = __half22float2(*(__half2*)&hv.w);
            acc = fmaf(f0.x, v0.x, acc);
            acc = fmaf(f0.y, v0.y, acc);
            acc = fmaf(f1.x, v0.z, acc);
            acc = fmaf(f1.y, v0.w, acc);
            acc = fmaf(f2.x, v1.x, acc);
            acc = fmaf(f2.y, v1.y, acc);
            acc = fmaf(f3.x, v1.z, acc);
            acc = fmaf(f3.y, v1.w, acc);
        }
    }
    #pragma unroll
    for (int o = 16; o > 0; o >>= 1) acc += __shfl_xor_sync(0xFFFFFFFFu, acc, o);
    if (lane == 0) {
        float mu = (row < NPTS) ? MU_SMALL : 0.5f;
        xout[row] = mu / acc;
    }
}

// ---------------- epilogue: P = Ef*U*V*8192 -> out; row max/argmax ----------------
__global__ __launch_bounds__(256) void epilogue_k(float* __restrict__ out) {
    int i = blockIdx.x;
    int t = threadIdx.x;
    float Ui = g_U[i] * SCALE_OUT;
    unsigned long long best = 0ull;
    for (int j = t; j < NP1; j += 256) {
        float p = g_Ef[(size_t)i * PAD + j] * Ui * g_V[j];
        out[(size_t)i * NP1 + j] = p;
        if (j < NPTS) {
            unsigned long long pk =
                ((unsigned long long)__float_as_uint(p) << 32) | (unsigned)(4095 - j);
            best = (pk > best) ? pk : best;
        }
    }
    __shared__ unsigned long long sb[256];
    sb[t] = best;
    __syncthreads();
    #pragma unroll
    for (int s = 128; s > 0; s >>= 1) {
        if (t < s) { if (sb[t + s] > sb[t]) sb[t] = sb[t + s]; }
        __syncthreads();
    }
    if (t == 0 && i < NPTS) g_rowbest[i] = sb[0];
}

// ---------------- column max/argmax: deterministic packed atomicMax ----------------
__global__ __launch_bounds__(256) void colmax_k(const float* __restrict__ out) {
    int c  = blockIdx.x * 256 + threadIdx.x;   // 0..4095
    int i0 = blockIdx.y * 128;
    unsigned long long best = 0ull;
    #pragma unroll 4
    for (int r = 0; r < 128; r++) {
        int i = i0 + r;
        float p = out[(size_t)i * NP1 + c];
        unsigned long long pk =
            ((unsigned long long)__float_as_uint(p) << 32) | (unsigned)(4095 - i);
        best = (pk > best) ? pk : best;
    }
    atomicMax(&g_colbest[c], best);
}

// ---------------- final: mutual checks, thresholds, tail outputs ----------------
__global__ __launch_bounds__(256) void final_k(float* __restrict__ out) {
    int idx = blockIdx.x * 256 + threadIdx.x;  // 0..4095
    if (idx >= NPTS) return;
    size_t base = (size_t)NP1 * NP1;

    // indices0 / mscores0 (row idx)
    unsigned long long rb = g_rowbest[idx];
    int   j0   = 4095 - (int)(unsigned)(rb & 0xFFFFFFFFull);
    float maxP = __uint_as_float((unsigned)(rb >> 32));
    unsigned long long cbj = g_colbest[j0];
    int   iback = 4095 - (int)(unsigned)(cbj & 0xFFFFFFFFull);
    bool  mutual0 = (iback == idx);
    float ms0 = mutual0 ? maxP : 0.0f;
    bool  valid0 = mutual0 && (ms0 > 0.2f);
    float idx0f = valid0 ? (float)j0 : -1.0f;

    // indices1 / mscores1 (col idx)
    unsigned long long cb = g_colbest[idx];
    int   i0 = 4095 - (int)(unsigned)(cb & 0xFFFFFFFFull);
    unsigned long long rbi = g_rowbest[i0];
    int   jback = 4095 - (int)(unsigned)(rbi & 0xFFFFFFFFull);
    float rmax  = __uint_as_float((unsigned)(rbi >> 32));
    bool  mutual1 = (jback == idx);     // mutual1 => mutual0[i0] automatically
    float ms1 = mutual1 ? rmax : 0.0f;
    bool  valid1 = mutual1 && (rmax > 0.2f);
    float idx1f = valid1 ? (float)i0 : -1.0f;

    out[base + idx]          = idx0f;
    out[base + 4096 + idx]   = idx1f;
    out[base + 8192 + idx]   = ms0;
    out[base + 12288 + idx]  = ms1;
}

// ---------------- launch ----------------
extern "C" void kernel_launch(void* const* d_in, const int* in_sizes, int n_in,
                              void* d_out, int out_size) {
    const float* A   = (const float*)d_in[0];   // mdesc0 (1,128,4096)
    const float* B   = (const float*)d_in[1];   // mdesc1 (1,128,4096)
    const float* bin = (const float*)d_in[2];   // bin_score scalar
    float* out = (float*)d_out;

    init_k<<<17, 256>>>(bin);
    gemm_exp_k<<<dim3(32, 32), 256>>>(A, B);
    transpose_k<<<dim3((NP1 + 31) / 32, (PAD + 31) / 32), dim3(32, 8)>>>();

    int passGrid = (NP1 + 15) / 16;   // 257 blocks, 16 rows each
    for (int it = 0; it < 100; it++) {
        sink_pass_k<<<passGrid, 512>>>(0);   // U = mu / (E  V)
        sink_pass_k<<<passGrid, 512>>>(1);   // V = nu / (E^T U)
    }

    epilogue_k<<<NP1, 256>>>(out);
    colmax_k<<<dim3(16, 32), 256>>>(out);
    final_k<<<16, 256>>>(out);
}

// round 4
// speedup vs baseline: 1.1367x; 1.1367x over previous
#include <cuda_runtime.h>
#include <cuda_fp16.h>
#include <cstdint>

#define NPTS 4096
#define NP1  4097
#define PAD  4104           // row stride (elements), 8-elem aligned -> 16B aligned rows for half
#define NBLK 148            // persistent grid: one block per SM, single wave
#define MU_SMALL (1.0f/8192.0f)
#define SCALE_OUT 8192.0f   // exp(-norm) = m+n
#define INV_SQRT_D 0.08838834764831845f  // 1/sqrt(128)

// ---------------- device scratch (no cudaMalloc allowed) ----------------
__device__ float              g_Ef [(size_t)NP1 * PAD];   // fp32 exp(couplings), padded
__device__ __half             g_Eh [(size_t)NP1 * PAD];   // fp16 copy (row-major)
__device__ __half             g_EhT[(size_t)NP1 * PAD];   // fp16 transpose
__device__ float              g_U[PAD];
__device__ float              g_V[PAD];
__device__ unsigned long long g_rowbest[NPTS];
__device__ unsigned long long g_colbest[NPTS];
__device__ unsigned           g_arrive;
__device__ volatile unsigned  g_release;

// ---------------- init: bins, pads, V=1, colbest=0, barrier reset ----------------
__global__ void init_k(const float* __restrict__ bin) {
    int idx = blockIdx.x * blockDim.x + threadIdx.x;
    if (idx == 0) { g_arrive = 0; g_release = 0; }
    float ea = __expf(bin[0]);
    __half eah = __float2half_rn(ea);
    __half zh  = __float2half_rn(0.0f);
    if (idx < PAD) {
        g_V[idx] = (idx < NP1) ? 1.0f : 0.0f;
        g_U[idx] = 0.0f;
    }
    if (idx < NPTS) g_colbest[idx] = 0ull;
    if (idx < NP1) {
        // bin column and bin row (corner covered by both, same value)
        g_Ef[(size_t)idx * PAD + NPTS] = ea;
        g_Eh[(size_t)idx * PAD + NPTS] = eah;
        g_Ef[(size_t)NPTS * PAD + idx] = ea;
        g_Eh[(size_t)NPTS * PAD + idx] = eah;
        // zero the padding columns so they never contribute to sums
        #pragma unroll
        for (int p = NP1; p < PAD; p++) {
            g_Ef[(size_t)idx * PAD + p] = 0.0f;
            g_Eh[(size_t)idx * PAD + p] = zh;
        }
    }
}

// ---------------- GEMM: C = (A^T B)/sqrt(128); E = exp(C) ----------------
__global__ __launch_bounds__(256) void gemm_exp_k(const float* __restrict__ A,
                                                  const float* __restrict__ B) {
    __shared__ float As[16][128];
    __shared__ float Bs[16][128];
    int tid = threadIdx.x;
    int tx = tid & 15;
    int ty = tid >> 4;
    int n0 = blockIdx.y * 128;
    int m0 = blockIdx.x * 128;

    float acc[8][8];
    #pragma unroll
    for (int i = 0; i < 8; i++)
        #pragma unroll
        for (int j = 0; j < 8; j++) acc[i][j] = 0.0f;

    for (int kk = 0; kk < 128; kk += 16) {
        #pragma unroll
        for (int p = 0; p < 2; p++) {
            int v = tid + p * 256;
            int r = v >> 5;
            int c4 = (v & 31) << 2;
            *(float4*)&As[r][c4] = *(const float4*)&A[(size_t)(kk + r) * 4096 + n0 + c4];
            *(float4*)&Bs[r][c4] = *(const float4*)&B[(size_t)(kk + r) * 4096 + m0 + c4];
        }
        __syncthreads();
        #pragma unroll
        for (int k = 0; k < 16; k++) {
            float a[8], b[8];
            *(float4*)&a[0] = *(float4*)&As[k][ty * 8];
            *(float4*)&a[4] = *(float4*)&As[k][ty * 8 + 4];
            *(float4*)&b[0] = *(float4*)&Bs[k][tx * 8];
            *(float4*)&b[4] = *(float4*)&Bs[k][tx * 8 + 4];
            #pragma unroll
            for (int i = 0; i < 8; i++)
                #pragma unroll
                for (int j = 0; j < 8; j++)
                    acc[i][j] = fmaf(a[i], b[j], acc[i][j]);
        }
        __syncthreads();
    }

    #pragma unroll
    for (int i = 0; i < 8; i++) {
        int n = n0 + ty * 8 + i;
        #pragma unroll
        for (int j = 0; j < 8; j++) {
            int m = m0 + tx * 8 + j;
            float e = __expf(acc[i][j] * INV_SQRT_D);
            g_Ef[(size_t)n * PAD + m] = e;
            g_Eh[(size_t)n * PAD + m] = __float2half_rn(e);
        }
    }
}

// ---------------- transpose Eh -> EhT (32x32 tiles) ----------------
__global__ void transpose_k() {
    __shared__ __half tile[32][33];
    int tx = threadIdx.x;
    int ty = threadIdx.y;
    int nBase = blockIdx.y * 32;
    int mBase = blockIdx.x * 32;
    #pragma unroll
    for (int jj = 0; jj < 32; jj += 8) {
        int n = nBase + ty + jj;
        int m = mBase + tx;
        __half v = __float2half_rn(0.0f);
        if (n < NP1 && m < PAD) v = g_Eh[(size_t)n * PAD + m];
        tile[ty + jj][tx] = v;
    }
    __syncthreads();
    #pragma unroll
    for (int jj = 0; jj < 32; jj += 8) {
        int m = mBase + ty + jj;
        int n = nBase + tx;
        if (m < NP1 && n < PAD) g_EhT[(size_t)m * PAD + n] = tile[tx][ty + jj];
    }
}

// ---------------- persistent Sinkhorn: 200 half-passes, one launch ----------------
// even pass: U = mu / (Eh  . V)      odd pass: V = nu / (EhT . U)
__global__ __launch_bounds__(1024, 1) void sink_persist_k() {
    __shared__ float sx[PAD];
    const int tid  = threadIdx.x;
    const int warp = tid >> 5;
    const int lane = tid & 31;
    const int row  = blockIdx.x + NBLK * warp;     // strided: <=28 active warps/block
    const bool active = (row < NP1);
    const float mu = (row < NPTS) ? MU_SMALL : 0.5f;
    const __half* rp_even = g_Eh  + (size_t)row * PAD;
    const __half* rp_odd  = g_EhT + (size_t)row * PAD;

    for (int pass = 0; pass < 200; pass++) {
        const int dir = pass & 1;
        const float* xin  = dir ? g_U : g_V;
        float*       xout = dir ? g_V : g_U;
        const __half* rp  = dir ? rp_odd : rp_even;

        // load x into shared, bypassing L1 (other blocks wrote it last phase)
        for (int idx = tid; idx < PAD; idx += 1024) sx[idx] = __ldcg(&xin[idx]);
        __syncthreads();

        if (active) {
            float acc = 0.0f;
            #pragma unroll 4
            for (int it = 0; it < 17; it++) {
                int base = (it * 32 + lane) * 8;
                if (base < PAD) {
                    uint4 hv = *(const uint4*)(rp + base);   // 8 halves
                    float4 v0 = *(float4*)&sx[base];
                    float4 v1 = *(float4*)&sx[base + 4];
                    float2 f0 = __half22float2(*(__half2*)&hv.x);
                    float2 f1 = __half22float2(*(__half2*)&hv.y);
                    float2 f2 = __half22float2(*(__half2*)&hv.z);
                    float2 f3 = __half22float2(*(__half2*)&hv.w);
                    acc = fmaf(f0.x, v0.x, acc);
                    acc = fmaf(f0.y, v0.y, acc);
                    acc = fmaf(f1.x, v0.z, acc);
                    acc = fmaf(f1.y, v0.w, acc);
                    acc = fmaf(f2.x, v1.x, acc);
                    acc = fmaf(f2.y, v1.y, acc);
                    acc = fmaf(f3.x, v1.z, acc);
                    acc = fmaf(f3.y, v1.w, acc);
                }
            }
            #pragma unroll
            for (int o = 16; o > 0; o >>= 1) acc += __shfl_xor_sync(0xFFFFFFFFu, acc, o);
            if (lane == 0) xout[row] = mu / acc;
        }

        // grid barrier (also protects the shared-x reload of the next phase)
        __syncthreads();
        if (tid == 0) {
            __threadfence();                       // publish xout writes
            unsigned prev = atomicAdd(&g_arrive, 1);
            if (prev == (unsigned)(gridDim.x - 1)) {
                g_arrive = 0;                      // safe: everyone has arrived
                __threadfence();
                g_release = (unsigned)(pass + 1);
            } else {
                while (g_release < (unsigned)(pass + 1)) { }
            }
        }
        __syncthreads();
    }
}

// ---------------- epilogue: P = Ef*U*V*8192 -> out; row max/argmax ----------------
__global__ __launch_bounds__(256) void epilogue_k(float* __restrict__ out) {
    int i = blockIdx.x;
    int t = threadIdx.x;
    float Ui = g_U[i] * SCALE_OUT;
    unsigned long long best = 0ull;
    for (int j = t; j < NP1; j += 256) {
        float p = g_Ef[(size_t)i * PAD + j] * Ui * g_V[j];
        out[(size_t)i * NP1 + j] = p;
        if (j < NPTS) {
            unsigned long long pk =
                ((unsigned long long)__float_as_uint(p) << 32) | (unsigned)(4095 - j);
            best = (pk > best) ? pk : best;
        }
    }
    __shared__ unsigned long long sb[256];
    sb[t] = best;
    __syncthreads();
    #pragma unroll
    for (int s = 128; s > 0; s >>= 1) {
        if (t < s) { if (sb[t + s] > sb[t]) sb[t] = sb[t + s]; }
        __syncthreads();
    }
    if (t == 0 && i < NPTS) g_rowbest[i] = sb[0];
}

// ---------------- column max/argmax: deterministic packed atomicMax ----------------
__global__ __launch_bounds__(256) void colmax_k(const float* __restrict__ out) {
    int c  = blockIdx.x * 256 + threadIdx.x;   // 0..4095
    int i0 = blockIdx.y * 128;
    unsigned long long best = 0ull;
    #pragma unroll 4
    for (int r = 0; r < 128; r++) {
        int i = i0 + r;
        float p = out[(size_t)i * NP1 + c];
        unsigned long long pk =
            ((unsigned long long)__float_as_uint(p) << 32) | (unsigned)(4095 - i);
        best = (pk > best) ? pk : best;
    }
    atomicMax(&g_colbest[c], best);
}

// ---------------- final: mutual checks, thresholds, tail outputs ----------------
__global__ __launch_bounds__(256) void final_k(float* __restrict__ out) {
    int idx = blockIdx.x * 256 + threadIdx.x;  // 0..4095
    if (idx >= NPTS) return;
    size_t base = (size_t)NP1 * NP1;

    unsigned long long rb = g_rowbest[idx];
    int   j0   = 4095 - (int)(unsigned)(rb & 0xFFFFFFFFull);
    float maxP = __uint_as_float((unsigned)(rb >> 32));
    unsigned long long cbj = g_colbest[j0];
    int   iback = 4095 - (int)(unsigned)(cbj & 0xFFFFFFFFull);
    bool  mutual0 = (iback == idx);
    float ms0 = mutual0 ? maxP : 0.0f;
    bool  valid0 = mutual0 && (ms0 > 0.2f);
    float idx0f = valid0 ? (float)j0 : -1.0f;

    unsigned long long cb = g_colbest[idx];
    int   i0 = 4095 - (int)(unsigned)(cb & 0xFFFFFFFFull);
    unsigned long long rbi = g_rowbest[i0];
    int   jback = 4095 - (int)(unsigned)(rbi & 0xFFFFFFFFull);
    float rmax  = __uint_as_float((unsigned)(rbi >> 32));
    bool  mutual1 = (jback == idx);
    float ms1 = mutual1 ? rmax : 0.0f;
    bool  valid1 = mutual1 && (rmax > 0.2f);
    float idx1f = valid1 ? (float)i0 : -1.0f;

    out[base + idx]          = idx0f;
    out[base + 4096 + idx]   = idx1f;
    out[base + 8192 + idx]   = ms0;
    out[base + 12288 + idx]  = ms1;
}

// ---------------- launch ----------------
extern "C" void kernel_launch(void* const* d_in, const int* in_sizes, int n_in,
                              void* d_out, int out_size) {
    const float* A   = (const float*)d_in[0];   // mdesc0 (1,128,4096)
    const float* B   = (const float*)d_in[1];   // mdesc1 (1,128,4096)
    const float* bin = (const float*)d_in[2];   // bin_score scalar
    float* out = (float*)d_out;

    init_k<<<17, 256>>>(bin);
    gemm_exp_k<<<dim3(32, 32), 256>>>(A, B);
    transpose_k<<<dim3((NP1 + 31) / 32, (PAD + 31) / 32), dim3(32, 8)>>>();

    sink_persist_k<<<NBLK, 1024>>>();           // all 200 half-passes in one launch

    epilogue_k<<<NP1, 256>>>(out);
    colmax_k<<<dim3(16, 32), 256>>>(out);
    final_k<<<16, 256>>>(out);
}